// round 11
// baseline (speedup 1.0000x reference)
#include <cuda_runtime.h>
#include <cuda_bf16.h>
#include <cstdint>

#define ITERS 3
#define EPSc 1e-8f
#define LN_EPSc 1e-5f
#define Mc 262144   // B*N
#define BSc 512     // B*S

// ---------------- scratch (device globals) ----------------------------------
__device__ __nv_bfloat16 g_a2 [67108864]; // [M,256] bf16 of LN(x)
__device__ __nv_bfloat16 g_wb2[131072];   // [512 n][256 k] bf16 K-major
__device__ __nv_bfloat16 g_kbufh[67108864];// K [B,H,N,DH] bf16
__device__ __nv_bfloat16 g_vbufh[67108864];// V [B,H,N,DH] bf16
__device__ float g_slots[131072];
__device__ float g_upd2 [131072];
__device__ float g_xg   [393216];
__device__ float g_hg   [393216];
__device__ float g_updpart[524288];        // [bh*4+chunk][8s][32dh]
__device__ float g_rspart [16384];         // [bh*4+chunk][8s]

__device__ __forceinline__ uint32_t smem_u32(const void* p) {
    uint32_t a;
    asm("{ .reg .u64 t; cvta.to.shared.u64 t, %1; cvt.u32.u64 %0, t; }" : "=r"(a) : "l"(p));
    return a;
}
__device__ __forceinline__ void cp_async16(uint32_t ds, const void* gp) {
    asm volatile("cp.async.cg.shared.global [%0], [%1], 16;" :: "r"(ds), "l"(gp));
}
#define CP_COMMIT() asm volatile("cp.async.commit_group;")
#define CP_WAIT1()  asm volatile("cp.async.wait_group 1;")
#define CP_WAIT0()  asm volatile("cp.async.wait_group 0;")
#define LDMX4(r0,r1,r2,r3,a) \
    asm volatile("ldmatrix.sync.aligned.m8n8.x4.shared.b16 {%0,%1,%2,%3}, [%4];" \
        : "=r"(r0),"=r"(r1),"=r"(r2),"=r"(r3) : "r"(a))
#define MMA16816(acc, a0,a1,a2,a3, b0,b1) \
    asm volatile("mma.sync.aligned.m16n8k16.row.col.f32.bf16.bf16.f32 " \
        "{%0,%1,%2,%3}, {%4,%5,%6,%7}, {%8,%9}, {%0,%1,%2,%3};" \
        : "+f"((acc)[0]), "+f"((acc)[1]), "+f"((acc)[2]), "+f"((acc)[3]) \
        : "r"(a0), "r"(a1), "r"(a2), "r"(a3), "r"(b0), "r"(b1))

// f32x2 packed helpers
typedef unsigned long long ull;
__device__ __forceinline__ ull pack2(float lo, float hi) {
    ull r;
    asm("mov.b64 %0, {%1, %2};" : "=l"(r) : "r"(__float_as_uint(lo)), "r"(__float_as_uint(hi)));
    return r;
}
__device__ __forceinline__ void unpack2(ull v, float& lo, float& hi) {
    uint32_t a, b;
    asm("mov.b64 {%0, %1}, %2;" : "=r"(a), "=r"(b) : "l"(v));
    lo = __uint_as_float(a); hi = __uint_as_float(b);
}
__device__ __forceinline__ ull fma2(ull a, ull b, ull c) {
    ull r;
    asm("fma.rn.f32x2 %0, %1, %2, %3;" : "=l"(r) : "l"(a), "l"(b), "l"(c));
    return r;
}

// ---------------- misc small kernels -----------------------------------------
__global__ void init_slots_kernel(const float* __restrict__ noise,
                                  const float* __restrict__ mean,
                                  const float* __restrict__ logv,
                                  float* __restrict__ slots)
{
    int idx = blockIdx.x * 256 + threadIdx.x;
    int d = idx & 255;
    slots[idx] = mean[d] + expf(logv[d]) * noise[idx];
}

// LN(inputs) -> bf16 [M,256]
__global__ void ln_kv_kernel(const float* __restrict__ src, __nv_bfloat16* __restrict__ dst,
                             const float* __restrict__ w, const float* __restrict__ b)
{
    int row = blockIdx.x * 8 + (threadIdx.x >> 5);
    int lane = threadIdx.x & 31;
    const float4* r4 = (const float4*)(src + (size_t)row * 256);
    float4 v0 = r4[lane], v1 = r4[lane + 32];
    float s  = v0.x + v0.y + v0.z + v0.w + v1.x + v1.y + v1.z + v1.w;
    float sq = v0.x*v0.x + v0.y*v0.y + v0.z*v0.z + v0.w*v0.w
             + v1.x*v1.x + v1.y*v1.y + v1.z*v1.z + v1.w*v1.w;
#pragma unroll
    for (int o = 16; o > 0; o >>= 1) {
        s  += __shfl_xor_sync(~0u, s,  o);
        sq += __shfl_xor_sync(~0u, sq, o);
    }
    float mean = s * (1.0f/256.0f);
    float rstd = rsqrtf(sq * (1.0f/256.0f) - mean*mean + LN_EPSc);
    float4 wa = ((const float4*)w)[lane], wb = ((const float4*)w)[lane+32];
    float4 ba = ((const float4*)b)[lane], bb = ((const float4*)b)[lane+32];
    float4 o0, o1;
    o0.x=(v0.x-mean)*rstd*wa.x+ba.x; o0.y=(v0.y-mean)*rstd*wa.y+ba.y;
    o0.z=(v0.z-mean)*rstd*wa.z+ba.z; o0.w=(v0.w-mean)*rstd*wa.w+ba.w;
    o1.x=(v1.x-mean)*rstd*wb.x+bb.x; o1.y=(v1.y-mean)*rstd*wb.y+bb.y;
    o1.z=(v1.z-mean)*rstd*wb.z+bb.z; o1.w=(v1.w-mean)*rstd*wb.w+bb.w;
    __nv_bfloat16* dr = dst + (size_t)row * 256;
    __nv_bfloat162 h0; h0.x = __float2bfloat16(o0.x); h0.y = __float2bfloat16(o0.y);
    __nv_bfloat162 h1; h1.x = __float2bfloat16(o0.z); h1.y = __float2bfloat16(o0.w);
    __nv_bfloat162 h2; h2.x = __float2bfloat16(o1.x); h2.y = __float2bfloat16(o1.y);
    __nv_bfloat162 h3; h3.x = __float2bfloat16(o1.z); h3.y = __float2bfloat16(o1.w);
    ((__nv_bfloat162*)(dr + lane*4))[0] = h0;
    ((__nv_bfloat162*)(dr + lane*4))[1] = h1;
    ((__nv_bfloat162*)(dr + 128 + lane*4))[0] = h2;
    ((__nv_bfloat162*)(dr + 128 + lane*4))[1] = h3;
}

// W -> [n][k] K-major bf16 (n<256: wk, else wv)
__global__ void prep_w_kernel(const float* __restrict__ wk, const float* __restrict__ wv,
                              __nv_bfloat16* __restrict__ B2)
{
    int n = blockIdx.x;
    int k = threadIdx.x;
    const float* W = (n < 256) ? wk : wv;
    B2[(size_t)n * 256 + k] = __float2bfloat16(W[(size_t)k * 256 + (n & 255)]);
}

// ---------------- K/V GEMM: pure bf16, 4 chunks of K=64 ----------------------
#define KV_SMEM (32768 * 2)
__global__ __launch_bounds__(256, 2)
void kv_gemm_mma(const __nv_bfloat16* __restrict__ A2, const __nv_bfloat16* __restrict__ B2,
                 const float* __restrict__ bk, const float* __restrict__ bv,
                 __nv_bfloat16* __restrict__ Kout, __nv_bfloat16* __restrict__ Vout)
{
    extern __shared__ char dsm[];
    uint32_t sbase = smem_u32(dsm);
    int tid = threadIdx.x, lane = tid & 31, wid = tid >> 5;
    int warp_m = wid & 1, warp_n = wid >> 1;
    int cb  = blockIdx.x;
    int m0  = blockIdx.y * 128;
    int mat = cb >> 1, nh = cb & 1;
    const float* bias = mat ? bv : bk;
    __nv_bfloat16* Out = mat ? Vout : Kout;

    float acc[4][4][4];
#pragma unroll
    for (int a = 0; a < 4; ++a)
#pragma unroll
        for (int b = 0; b < 4; ++b)
#pragma unroll
            for (int r = 0; r < 4; ++r) acc[a][b][r] = 0.0f;

    int lr = tid >> 3, lj = tid & 7;
    int brow_g = mat * 256 + nh * 128;

    int l7 = lane & 7, l15 = lane & 15, lhA = lane >> 4;
    int nrow_loc = (lane >> 4) * 8 + l7, hB = (lane >> 3) & 1;
    uint32_t aRow[4], bRow[2];
#pragma unroll
    for (int mt = 0; mt < 4; ++mt) aRow[mt] = (uint32_t)(warp_m*64 + mt*16 + l15) << 7;
#pragma unroll
    for (int g = 0; g < 2; ++g) bRow[g] = (uint32_t)(warp_n*32 + g*16 + nrow_loc) << 7;

#define LOAD_CHUNK(c, stg) do {                                               \
    uint32_t sa = sbase + (stg)*32768;                                        \
    int ko = (c)*64;                                                          \
    _Pragma("unroll")                                                         \
    for (int i = 0; i < 4; ++i) {                                             \
        int r = lr + i*32;                                                    \
        uint32_t so = (r<<7) + ((lj ^ (r&7))<<4);                             \
        cp_async16(sa + so, A2 + (size_t)(m0 + r)*256 + ko + lj*8);           \
        cp_async16(sa + 16384 + so, B2 + (size_t)(brow_g + r)*256 + ko + lj*8);\
    }                                                                         \
    CP_COMMIT();                                                              \
} while (0)

    LOAD_CHUNK(0, 0);
    LOAD_CHUNK(1, 1);

    for (int c = 0; c < 4; ++c) {
        if (c == 3) { CP_WAIT0(); } else { CP_WAIT1(); }
        __syncthreads();
        uint32_t sa = sbase + (c & 1) * 32768;
#pragma unroll
        for (int ks = 0; ks < 4; ++ks) {
            uint32_t achk = (uint32_t)(((2*ks + lhA) ^ l7) << 4);
            uint32_t bchk = (uint32_t)(((2*ks + hB)  ^ l7) << 4);
            uint32_t af[4][4], bf[2][4];
#pragma unroll
            for (int mt = 0; mt < 4; ++mt)
                LDMX4(af[mt][0], af[mt][1], af[mt][2], af[mt][3], sa + aRow[mt] + achk);
#pragma unroll
            for (int g = 0; g < 2; ++g)
                LDMX4(bf[g][0], bf[g][1], bf[g][2], bf[g][3], sa + 16384 + bRow[g] + bchk);
#pragma unroll
            for (int mt = 0; mt < 4; ++mt)
#pragma unroll
                for (int nt = 0; nt < 4; ++nt)
                    MMA16816(acc[mt][nt], af[mt][0], af[mt][1], af[mt][2], af[mt][3],
                             bf[nt>>1][(nt&1)*2], bf[nt>>1][(nt&1)*2+1]);
        }
        __syncthreads();
        if (c + 2 < 4) LOAD_CHUNK(c + 2, c & 1);
    }

    int col_base = nh * 128 + warp_n * 32;
    int h = col_base >> 5;
#pragma unroll
    for (int mt = 0; mt < 4; ++mt) {
#pragma unroll
        for (int half = 0; half < 2; ++half) {
            int m = m0 + warp_m * 64 + mt * 16 + (lane >> 2) + half * 8;
            int bi = m >> 12, nn = m & 4095;
            __nv_bfloat16* dst = Out + ((size_t)(bi * 8 + h) * 4096 + nn) * 32;
#pragma unroll
            for (int nt = 0; nt < 4; ++nt) {
                int dh = nt * 8 + (lane & 3) * 2;
                __nv_bfloat162 o;
                o.x = __float2bfloat16(acc[mt][nt][half*2+0] + bias[col_base + dh]);
                o.y = __float2bfloat16(acc[mt][nt][half*2+1] + bias[col_base + dh + 1]);
                *(__nv_bfloat162*)(dst + dh) = o;
            }
        }
    }
#undef LOAD_CHUNK
}

// ---------------- small GEMM (512 rows) ---------------------------------------
// modes: 0 plain, 4 virtual-A (A=upd_part summed*inv_rs from resid=rs_part)
__global__ __launch_bounds__(256)
void gemm512_kernel(const float* __restrict__ Ain, const float* __restrict__ Win,
                    const float* __restrict__ biasin, float* __restrict__ outin,
                    int Ncols, int mode, const float* __restrict__ resid,
                    const float* __restrict__ lnw, const float* __restrict__ lnb,
                    const float* __restrict__ A2, const float* __restrict__ W2,
                    const float* __restrict__ bias2, float* __restrict__ out2,
                    int y2)
{
    __shared__ float As[64][36];
    __shared__ float Bs[64][68];
    __shared__ float s_mean[32], s_rstd[32];
    __shared__ float s_inv[256];
    int tid = threadIdx.x, tx = tid & 31, ty = tid >> 5;
    int c0 = tx*2, r0 = ty*4;
    int m0 = blockIdx.x * 32;
    int yb = blockIdx.y;
    const float* A = Ain; const float* W = Win; const float* bias = biasin;
    float* out = outin;
    if (yb >= y2) { A = A2; W = W2; bias = bias2; out = out2; yb -= y2; }
    int n0 = yb * 64;
    int do_ln = (lnw != nullptr);

    if (do_ln) {
        int r = ty * 4 + (tx >> 3);
        const float4* rp = (const float4*)(A + (size_t)(m0 + r) * 256);
        float s = 0.0f, sq = 0.0f;
        for (int j = (tx & 7); j < 64; j += 8) {
            float4 v = rp[j];
            s  += v.x + v.y + v.z + v.w;
            sq += v.x*v.x + v.y*v.y + v.z*v.z + v.w*v.w;
        }
#pragma unroll
        for (int o = 4; o > 0; o >>= 1) {
            s  += __shfl_xor_sync(~0u, s,  o);
            sq += __shfl_xor_sync(~0u, sq, o);
        }
        if ((tx & 7) == 0) {
            float mean = s * (1.0f/256.0f);
            s_mean[r] = mean;
            s_rstd[r] = rsqrtf(sq * (1.0f/256.0f) - mean*mean + LN_EPSc);
        }
    }
    if (mode == 4) {
        int r = tid >> 3, hh = tid & 7;
        int m = m0 + r, b = m >> 3, s = m & 7;
        int bh = b * 8 + hh;
        float t = resid[(size_t)(bh*4+0)*8 + s] + resid[(size_t)(bh*4+1)*8 + s]
                + resid[(size_t)(bh*4+2)*8 + s] + resid[(size_t)(bh*4+3)*8 + s];
        s_inv[r*8 + hh] = 1.0f / fmaxf(t, 1e-12f);
    }
    __syncthreads();

    float acc[4][2] = {};
    for (int kt = 0; kt < 4; ++kt) {
        __syncthreads();
#pragma unroll
        for (int i = 0; i < 2; ++i) {
            int fid = tid*2 + i, ar = fid >> 4, kq = fid & 15;
            float4 va;
            if (mode == 4) {
                int m = m0 + ar, b = m >> 3, s = m & 7;
                int c = kt*64 + kq*4;
                int h = c >> 5, cc = c & 31;
                size_t base = ((size_t)(b*8 + h) * 4) * 256 + s*32 + cc;
                float4 v0 = *(const float4*)(A + base);
                float4 v1 = *(const float4*)(A + base + 256);
                float4 v2 = *(const float4*)(A + base + 512);
                float4 v3 = *(const float4*)(A + base + 768);
                float iv = s_inv[ar*8 + h];
                va.x = (v0.x+v1.x+v2.x+v3.x)*iv;
                va.y = (v0.y+v1.y+v2.y+v3.y)*iv;
                va.z = (v0.z+v1.z+v2.z+v3.z)*iv;
                va.w = (v0.w+v1.w+v2.w+v3.w)*iv;
            } else {
                va = *(const float4*)(A + (size_t)(m0+ar)*256 + kt*64 + kq*4);
                if (do_ln) {
                    float mn = s_mean[ar], rs = s_rstd[ar];
                    float4 lw = *(const float4*)(lnw + kt*64 + kq*4);
                    float4 lb = *(const float4*)(lnb + kt*64 + kq*4);
                    va.x = (va.x - mn)*rs*lw.x + lb.x;
                    va.y = (va.y - mn)*rs*lw.y + lb.y;
                    va.z = (va.z - mn)*rs*lw.z + lb.z;
                    va.w = (va.w - mn)*rs*lw.w + lb.w;
                }
            }
            As[kq*4+0][ar]=va.x; As[kq*4+1][ar]=va.y; As[kq*4+2][ar]=va.z; As[kq*4+3][ar]=va.w;
        }
#pragma unroll
        for (int j = 0; j < 4; ++j) {
            int fid = tid + j*256, br = fid >> 4, c4 = fid & 15;
            *(float4*)&Bs[br][c4*4] = *(const float4*)(W + (size_t)(kt*64+br)*Ncols + n0 + c4*4);
        }
        __syncthreads();
#pragma unroll 8
        for (int k = 0; k < 64; ++k) {
            float4 a4 = *(const float4*)&As[k][r0];
            float2 b2 = *(const float2*)&Bs[k][c0];
            acc[0][0]+=a4.x*b2.x; acc[0][1]+=a4.x*b2.y;
            acc[1][0]+=a4.y*b2.x; acc[1][1]+=a4.y*b2.y;
            acc[2][0]+=a4.z*b2.x; acc[2][1]+=a4.z*b2.y;
            acc[3][0]+=a4.w*b2.x; acc[3][1]+=a4.w*b2.y;
        }
    }
#pragma unroll
    for (int i = 0; i < 4; ++i)
#pragma unroll
        for (int j = 0; j < 2; ++j) {
            int m = m0 + r0 + i, n = n0 + c0 + j;
            float v = acc[i][j] + bias[n];
            out[(size_t)m*Ncols + n] = v;
        }
}

// ---------------- attention: fused LN+qproj, f32x2 pass2 ----------------------
// smem: attn2 u64[4][1024] | q_s f[256] | sln f[2048] | red f[64] | red2 f[2048]
#define ATT_SMEM (32768 + 1024 + 8192 + 256 + 8192)
__global__ __launch_bounds__(256)
void attention_part(const float* __restrict__ slots,
                    const float* __restrict__ lsw, const float* __restrict__ lsb,
                    const float* __restrict__ wq, const float* __restrict__ bq,
                    const __nv_bfloat16* __restrict__ Kh, const __nv_bfloat16* __restrict__ Vh,
                    float* __restrict__ upd_part, float* __restrict__ rs_part,
                    float* __restrict__ attn_out, int write_attn)
{
    extern __shared__ char smraw[];
    ull*   attn2 = (ull*)smraw;              // [4][1024]
    float* q_s   = (float*)(attn2 + 4096);   // [8][32]
    float* sln   = q_s + 256;                // [8][256]
    float* red   = sln + 2048;               // [8][8]
    float* red2  = red + 64;                 // [8][8][32]

    int bh = blockIdx.x, chunk = blockIdx.y;
    int b = bh >> 3, h = bh & 7;
    int tid = threadIdx.x, lane = tid & 31, wid = tid >> 5;
    int n0 = chunk * 1024;

    // LN(slots[b][wid]) -> sln (warp w handles slot row s=w)
    {
        const float4* r4 = (const float4*)(slots + (size_t)(b*8 + wid) * 256);
        float4 v0 = r4[lane], v1 = r4[lane + 32];
        float s  = v0.x + v0.y + v0.z + v0.w + v1.x + v1.y + v1.z + v1.w;
        float sq = v0.x*v0.x + v0.y*v0.y + v0.z*v0.z + v0.w*v0.w
                 + v1.x*v1.x + v1.y*v1.y + v1.z*v1.z + v1.w*v1.w;
#pragma unroll
        for (int o = 16; o > 0; o >>= 1) {
            s  += __shfl_xor_sync(~0u, s,  o);
            sq += __shfl_xor_sync(~0u, sq, o);
        }
        float mean = s * (1.0f/256.0f);
        float rstd = rsqrtf(sq * (1.0f/256.0f) - mean*mean + LN_EPSc);
        float4 wa = ((const float4*)lsw)[lane], wb = ((const float4*)lsw)[lane+32];
        float4 ba = ((const float4*)lsb)[lane], bb = ((const float4*)lsb)[lane+32];
        float4 o0, o1;
        o0.x=(v0.x-mean)*rstd*wa.x+ba.x; o0.y=(v0.y-mean)*rstd*wa.y+ba.y;
        o0.z=(v0.z-mean)*rstd*wa.z+ba.z; o0.w=(v0.w-mean)*rstd*wa.w+ba.w;
        o1.x=(v1.x-mean)*rstd*wb.x+bb.x; o1.y=(v1.y-mean)*rstd*wb.y+bb.y;
        o1.z=(v1.z-mean)*rstd*wb.z+bb.z; o1.w=(v1.w-mean)*rstd*wb.w+bb.w;
        float4* d4 = (float4*)(sln + wid*256);
        d4[lane] = o0; d4[lane+32] = o1;
    }
    __syncthreads();
    // q[s=wid][dh=lane] = (LN(slots) @ wq + bq) * 1/16
    {
        int c = h*32 + lane;
        float acc = bq[c];
        const float* sr = sln + wid*256;
        for (int k = 0; k < 256; k += 8) {
            float4 s0 = *(const float4*)(sr + k);
            float4 s1 = *(const float4*)(sr + k + 4);
            acc += s0.x*wq[(size_t)(k+0)*256+c] + s0.y*wq[(size_t)(k+1)*256+c]
                 + s0.z*wq[(size_t)(k+2)*256+c] + s0.w*wq[(size_t)(k+3)*256+c]
                 + s1.x*wq[(size_t)(k+4)*256+c] + s1.y*wq[(size_t)(k+5)*256+c]
                 + s1.z*wq[(size_t)(k+6)*256+c] + s1.w*wq[(size_t)(k+7)*256+c];
        }
        q_s[wid*32 + lane] = acc * 0.0625f;
    }
    __syncthreads();

    // pass1: dots + softmax(S) + eps; store s-paired u64
    float rs[8] = {};
    const __nv_bfloat16* Kb = Kh + (size_t)bh * 4096 * 32;
    for (int it = 0; it < 4; ++it) {
        int nl = it*256 + tid;
        const __nv_bfloat16* kr = Kb + (size_t)(n0 + nl) * 32;
        float d[8] = {};
#pragma unroll
        for (int c4 = 0; c4 < 4; ++c4) {
            float4 raw = *(const float4*)(kr + c4*8);
            const __nv_bfloat162* kp = (const __nv_bfloat162*)&raw;
            float2 k0 = __bfloat1622float2(kp[0]);
            float2 k1 = __bfloat1622float2(kp[1]);
            float2 k2 = __bfloat1622float2(kp[2]);
            float2 k3 = __bfloat1622float2(kp[3]);
#pragma unroll
            for (int s = 0; s < 8; ++s) {
                float4 qa = *(const float4*)(q_s + s*32 + c4*8);
                float4 qb = *(const float4*)(q_s + s*32 + c4*8 + 4);
                d[s] += k0.x*qa.x + k0.y*qa.y + k1.x*qa.z + k1.y*qa.w
                      + k2.x*qb.x + k2.y*qb.y + k3.x*qb.z + k3.y*qb.w;
            }
        }
        float mx = d[0];
#pragma unroll
        for (int s = 1; s < 8; ++s) mx = fmaxf(mx, d[s]);
        float e[8], sum = 0.0f;
#pragma unroll
        for (int s = 0; s < 8; ++s) { e[s] = __expf(d[s]-mx); sum += e[s]; }
        float inv = __fdividef(1.0f, sum);
        float pr[8];
#pragma unroll
        for (int s = 0; s < 8; ++s) { pr[s] = e[s]*inv + EPSc; rs[s] += pr[s]; }
#pragma unroll
        for (int p = 0; p < 4; ++p)
            attn2[p*1024 + nl] = pack2(pr[2*p], pr[2*p+1]);
    }
#pragma unroll
    for (int s = 0; s < 8; ++s)
#pragma unroll
        for (int o = 16; o > 0; o >>= 1) rs[s] += __shfl_xor_sync(~0u, rs[s], o);
    if (lane == 0)
#pragma unroll
        for (int s = 0; s < 8; ++s) red[wid*8 + s] = rs[s];
    __syncthreads();
    if (tid < 8) {
        float t = 0.0f;
#pragma unroll
        for (int w = 0; w < 8; ++w) t += red[w*8 + tid];
        rs_part[(size_t)(bh*4 + chunk)*8 + tid] = t;
    }

    // pass2: f32x2, warp w owns n-substripe [w*128, (w+1)*128)
    {
        const __nv_bfloat16* Vb = Vh + (size_t)bh * 4096 * 32;
        ull acc2[4] = {0,0,0,0};
        int nb = wid * 128;
        for (int nl = nb; nl < nb + 128; nl += 4) {
            ulonglong2 a0[4], a1[4];
#pragma unroll
            for (int p = 0; p < 4; ++p) {
                const ulonglong2* ap = (const ulonglong2*)(attn2 + p*1024 + nl);
                a0[p] = ap[0]; a1[p] = ap[1];
            }
            int n = n0 + nl;
            float v0 = __bfloat162float(Vb[(size_t)(n+0)*32 + lane]);
            float v1 = __bfloat162float(Vb[(size_t)(n+1)*32 + lane]);
            float v2 = __bfloat162float(Vb[(size_t)(n+2)*32 + lane]);
            float v3 = __bfloat162float(Vb[(size_t)(n+3)*32 + lane]);
            ull vp0 = pack2(v0, v0), vp1 = pack2(v1, v1);
            ull vp2 = pack2(v2, v2), vp3 = pack2(v3, v3);
#pragma unroll
            for (int p = 0; p < 4; ++p) {
                acc2[p] = fma2(a0[p].x, vp0, acc2[p]);
                acc2[p] = fma2(a0[p].y, vp1, acc2[p]);
                acc2[p] = fma2(a1[p].x, vp2, acc2[p]);
                acc2[p] = fma2(a1[p].y, vp3, acc2[p]);
            }
        }
        float acc[8];
#pragma unroll
        for (int p = 0; p < 4; ++p) unpack2(acc2[p], acc[2*p], acc[2*p+1]);
#pragma unroll
        for (int s = 0; s < 8; ++s) red2[(wid*8 + s)*32 + lane] = acc[s];
    }
    __syncthreads();
    {
        int s = tid >> 5, dh = tid & 31;
        float t = 0.0f;
#pragma unroll
        for (int w = 0; w < 8; ++w) t += red2[(w*8 + s)*32 + dh];
        upd_part[(size_t)(bh*4 + chunk)*256 + s*32 + dh] = t;
    }

    if (write_attn) {  // unnormalized; attn_scale normalizes later
        const float* smf = (const float*)attn2;
        float* ao = attn_out + (size_t)bh * 32768 + n0;
        for (int i = tid; i < 8192; i += 256) {
            int s = i >> 10, n = i & 1023;
            ao[s * 4096 + n] = smf[(((s>>1)*1024) + n)*2 + (s&1)];
        }
    }
}

__global__ void attn_scale(float* __restrict__ ao, const float* __restrict__ rsp)
{
    int bh = blockIdx.x, tid = threadIdx.x;
    __shared__ float inv[8];
    if (tid < 8) {
        float t = 0.0f;
#pragma unroll
        for (int c = 0; c < 4; ++c) t += rsp[(size_t)(bh*4 + c)*8 + tid];
        inv[tid] = 1.0f / fmaxf(t, 1e-12f);
    }
    __syncthreads();
    float* p = ao + (size_t)bh * 32768;
    for (int i = tid; i < 32768; i += 256)
        p[i] *= inv[i >> 12];
}

__global__ void gru_combine_kernel(const float* __restrict__ xg,
                                   const float* __restrict__ hg,
                                   float* __restrict__ slots)
{
    int idx = blockIdx.x * 256 + threadIdx.x;
    int row = idx >> 8, c = idx & 255;
    const float* x = xg + (size_t)row * 768;
    const float* h = hg + (size_t)row * 768;
    float r = 1.0f / (1.0f + expf(-(x[c]     + h[c])));
    float z = 1.0f / (1.0f + expf(-(x[256+c] + h[256+c])));
    float n = tanhf(x[512+c] + r * h[512+c]);
    slots[idx] = (1.0f - z) * n + z * slots[idx];
}

// ---------------- fused FFN: out = slots + relu(LN(slots)@w1+b1)@w2 + b2 ------
__global__ __launch_bounds__(256)
void ffn_fused(const float* __restrict__ slots,
               const float* __restrict__ w1, const float* __restrict__ b1,
               const float* __restrict__ w2, const float* __restrict__ b2,
               const float* __restrict__ lffw, const float* __restrict__ lffb,
               float* __restrict__ outp)
{
    __shared__ float ff_s[2048], h1_s[2048];
    int tid = threadIdx.x, lane = tid & 31, wid = tid >> 5;
    int m0 = blockIdx.x * 8;

    {   // LN row m0+wid
        const float4* r4 = (const float4*)(slots + (size_t)(m0 + wid) * 256);
        float4 v0 = r4[lane], v1 = r4[lane + 32];
        float s  = v0.x + v0.y + v0.z + v0.w + v1.x + v1.y + v1.z + v1.w;
        float sq = v0.x*v0.x + v0.y*v0.y + v0.z*v0.z + v0.w*v0.w
                 + v1.x*v1.x + v1.y*v1.y + v1.z*v1.z + v1.w*v1.w;
#pragma unroll
        for (int o = 16; o > 0; o >>= 1) {
            s  += __shfl_xor_sync(~0u, s,  o);
            sq += __shfl_xor_sync(~0u, sq, o);
        }
        float mean = s * (1.0f/256.0f);
        float rstd = rsqrtf(sq * (1.0f/256.0f) - mean*mean + LN_EPSc);
        float4 wa = ((const float4*)lffw)[lane], wb = ((const float4*)lffw)[lane+32];
        float4 ba = ((const float4*)lffb)[lane], bb = ((const float4*)lffb)[lane+32];
        float4 o0, o1;
        o0.x=(v0.x-mean)*rstd*wa.x+ba.x; o0.y=(v0.y-mean)*rstd*wa.y+ba.y;
        o0.z=(v0.z-mean)*rstd*wa.z+ba.z; o0.w=(v0.w-mean)*rstd*wa.w+ba.w;
        o1.x=(v1.x-mean)*rstd*wb.x+bb.x; o1.y=(v1.y-mean)*rstd*wb.y+bb.y;
        o1.z=(v1.z-mean)*rstd*wb.z+bb.z; o1.w=(v1.w-mean)*rstd*wb.w+bb.w;
        float4* d4 = (float4*)(ff_s + wid*256);
        d4[lane] = o0; d4[lane+32] = o1;
    }
    __syncthreads();

    int r = tid >> 6;            // 0..3 (and r+4)
    int c0 = (tid & 63) * 4;     // 0..252
    {   // stage 1: h1 = relu(ff @ w1 + b1)
        float4 a0 = *(const float4*)(b1 + c0);
        float4 a1 = a0;
        const float* f0 = ff_s + r*256;
        const float* f1 = ff_s + (r+4)*256;
        for (int k = 0; k < 256; k += 4) {
            float4 x0 = *(const float4*)(f0 + k);
            float4 x1 = *(const float4*)(f1 + k);
#pragma unroll
            for (int j = 0; j < 4; ++j) {
                float4 wv = *(const float4*)(w1 + (size_t)(k+j)*256 + c0);
                float e0 = j==0?x0.x:(j==1?x0.y:(j==2?x0.z:x0.w));
                float e1 = j==0?x1.x:(j==1?x1.y:(j==2?x1.z:x1.w));
                a0.x += e0*wv.x; a0.y += e0*wv.y; a0.z += e0*wv.z; a0.w += e0*wv.w;
                a1.x += e1*wv.x; a1.y += e1*wv.y; a1.z += e1*wv.z; a1.w += e1*wv.w;
            }
        }
        a0.x=fmaxf(a0.x,0.f); a0.y=fmaxf(a0.y,0.f); a0.z=fmaxf(a0.z,0.f); a0.w=fmaxf(a0.w,0.f);
        a1.x=fmaxf(a1.x,0.f); a1.y=fmaxf(a1.y,0.f); a1.z=fmaxf(a1.z,0.f); a1.w=fmaxf(a1.w,0.f);
        *(float4*)(h1_s + r*256 + c0)     = a0;
        *(float4*)(h1_s + (r+4)*256 + c0) = a1;
    }
    __syncthreads();
    {   // stage 2: out = slots + h1 @ w2 + b2
        float4 a0 = *(const float4*)(b2 + c0);
        float4 a1 = a0;
        const float* f0 = h1_s + r*256;
        const float* f1 = h1_s + (r+4)*256;
        for (int k = 0; k < 256; k += 4) {
            float4 x0 = *(const float4*)(f0 + k);
            float4 x1 = *(const float4*)(f1 + k);
#pragma unroll
            for (int j = 0; j < 4; ++j) {
                float4 wv = *(const float4*)(w2 + (size_t)(k+j)*256 + c0);
                float e0 = j==0?x0.x:(j==1?x0.y:(j==2?x0.z:x0.w));
                float e1 = j==0?x1.x:(j==1?x1.y:(j==2?x1.z:x1.w));
                a0.x += e0*wv.x; a0.y += e0*wv.y; a0.z += e0*wv.z; a0.w += e0*wv.w;
                a1.x += e1*wv.x; a1.y += e1*wv.y; a1.z += e1*wv.z; a1.w += e1*wv.w;
            }
        }
        size_t o0 = (size_t)(m0 + r)*256 + c0;
        size_t o1 = (size_t)(m0 + r + 4)*256 + c0;
        float4 s0 = *(const float4*)(slots + o0);
        float4 s1 = *(const float4*)(slots + o1);
        a0.x += s0.x; a0.y += s0.y; a0.z += s0.z; a0.w += s0.w;
        a1.x += s1.x; a1.y += s1.y; a1.z += s1.z; a1.w += s1.w;
        *(float4*)(outp + o0) = a0;
        *(float4*)(outp + o1) = a1;
    }
}

// ---------------- launcher ----------------------------------------------------
extern "C" void kernel_launch(void* const* d_in, const int* in_sizes, int n_in,
                              void* d_out, int out_size)
{
    const float* inp   = (const float*)d_in[0];
    const float* noise = (const float*)d_in[1];
    const float* smean = (const float*)d_in[2];
    const float* slogv = (const float*)d_in[3];
    const float* wq = (const float*)d_in[4];  const float* bq = (const float*)d_in[5];
    const float* wk = (const float*)d_in[6];  const float* bk = (const float*)d_in[7];
    const float* wv = (const float*)d_in[8];  const float* bv = (const float*)d_in[9];
    const float* wo = (const float*)d_in[10]; const float* bo = (const float*)d_in[11];
    const float* w_ih = (const float*)d_in[12]; const float* b_ih = (const float*)d_in[13];
    const float* w_hh = (const float*)d_in[14]; const float* b_hh = (const float*)d_in[15];
    const float* w1 = (const float*)d_in[16]; const float* b1 = (const float*)d_in[17];
    const float* w2 = (const float*)d_in[18]; const float* b2 = (const float*)d_in[19];
    const float* lin_w = (const float*)d_in[20]; const float* lin_b = (const float*)d_in[21];
    const float* ls_w  = (const float*)d_in[22]; const float* ls_b  = (const float*)d_in[23];
    const float* lff_w = (const float*)d_in[24]; const float* lff_b = (const float*)d_in[25];

    float* out      = (float*)d_out;
    float* attn_out = out + 131072;

    __nv_bfloat16 *a2, *wb2, *kbh, *vbh;
    float *slots,*upd2,*xg,*hg,*updp,*rsp;
    cudaGetSymbolAddress((void**)&a2,   g_a2);
    cudaGetSymbolAddress((void**)&wb2,  g_wb2);
    cudaGetSymbolAddress((void**)&kbh,  g_kbufh);
    cudaGetSymbolAddress((void**)&vbh,  g_vbufh);
    cudaGetSymbolAddress((void**)&slots,g_slots);
    cudaGetSymbolAddress((void**)&upd2, g_upd2);
    cudaGetSymbolAddress((void**)&xg,   g_xg);
    cudaGetSymbolAddress((void**)&hg,   g_hg);
    cudaGetSymbolAddress((void**)&updp, g_updpart);
    cudaGetSymbolAddress((void**)&rsp,  g_rspart);

    cudaFuncSetAttribute(attention_part,
                         cudaFuncAttributeMaxDynamicSharedMemorySize, (int)ATT_SMEM);
    cudaFuncSetAttribute(kv_gemm_mma,
                         cudaFuncAttributeMaxDynamicSharedMemorySize, KV_SMEM);

    init_slots_kernel<<<BSc, 256>>>(noise, smean, slogv, slots);
    prep_w_kernel<<<512, 256>>>(wk, wv, wb2);
    ln_kv_kernel<<<Mc/8, 256>>>(inp, a2, lin_w, lin_b);
    kv_gemm_mma<<<dim3(4, Mc/128), 256, KV_SMEM>>>(a2, wb2, bk, bv, kbh, vbh);

    for (int it = 0; it < ITERS; ++it) {
        int last = (it == ITERS - 1);
        attention_part<<<dim3(512, 4), 256, ATT_SMEM>>>(
            slots, ls_w, ls_b, wq, bq, kbh, vbh, updp, rsp, attn_out, last);
        gemm512_kernel<<<dim3(16, 4), 256>>>(updp, wo, bo, upd2, 256, 4, rsp,
                                             nullptr, nullptr, nullptr, nullptr, nullptr, nullptr, 9999);
        gemm512_kernel<<<dim3(16, 24), 256>>>(upd2, w_ih, b_ih, xg, 768, 0, nullptr,
                                              nullptr, nullptr, slots, w_hh, b_hh, hg, 12);
        gru_combine_kernel<<<BSc, 256>>>(xg, hg, slots);
        ffn_fused<<<64, 256>>>(slots, w1, b1, w2, b2, lff_w, lff_b, last ? out : slots);
        if (last) attn_scale<<<512, 256>>>(attn_out, rsp);
    }
}

// round 12
// speedup vs baseline: 1.3448x; 1.3448x over previous
#include <cuda_runtime.h>
#include <cuda_bf16.h>
#include <cstdint>

#define ITERS 3
#define EPSc 1e-8f
#define LN_EPSc 1e-5f
#define Mc 262144   // B*N
#define BSc 512     // B*S

// ---------------- scratch (device globals) ----------------------------------
__device__ __nv_bfloat16 g_a2 [67108864]; // [M,256] bf16 of LN(x)
__device__ __nv_bfloat16 g_wb2[131072];   // [512 n][256 k] bf16 K-major
__device__ __nv_bfloat16 g_kbufh[67108864];// K [B,H,N,DH] bf16
__device__ __nv_bfloat16 g_vbufh[67108864];// V [B,H,N,DH] bf16
__device__ float g_slots[131072];
__device__ float g_q    [131072];
__device__ float g_upd2 [131072];
__device__ float g_h1   [131072];
__device__ float g_xg   [393216];
__device__ float g_hg   [393216];
__device__ float g_updpart[524288];        // [bh*4+chunk][8s][32dh]
__device__ float g_rspart [16384];         // [bh*4+chunk][8s]

__device__ __forceinline__ uint32_t smem_u32(const void* p) {
    uint32_t a;
    asm("{ .reg .u64 t; cvta.to.shared.u64 t, %1; cvt.u32.u64 %0, t; }" : "=r"(a) : "l"(p));
    return a;
}
__device__ __forceinline__ void cp_async16(uint32_t ds, const void* gp) {
    asm volatile("cp.async.cg.shared.global [%0], [%1], 16;" :: "r"(ds), "l"(gp));
}
#define CP_COMMIT() asm volatile("cp.async.commit_group;")
#define CP_WAIT1()  asm volatile("cp.async.wait_group 1;")
#define CP_WAIT0()  asm volatile("cp.async.wait_group 0;")
#define LDMX4(r0,r1,r2,r3,a) \
    asm volatile("ldmatrix.sync.aligned.m8n8.x4.shared.b16 {%0,%1,%2,%3}, [%4];" \
        : "=r"(r0),"=r"(r1),"=r"(r2),"=r"(r3) : "r"(a))
#define MMA16816(acc, a0,a1,a2,a3, b0,b1) \
    asm volatile("mma.sync.aligned.m16n8k16.row.col.f32.bf16.bf16.f32 " \
        "{%0,%1,%2,%3}, {%4,%5,%6,%7}, {%8,%9}, {%0,%1,%2,%3};" \
        : "+f"((acc)[0]), "+f"((acc)[1]), "+f"((acc)[2]), "+f"((acc)[3]) \
        : "r"(a0), "r"(a1), "r"(a2), "r"(a3), "r"(b0), "r"(b1))

// ---------------- misc small kernels -----------------------------------------
__global__ void init_slots_kernel(const float* __restrict__ noise,
                                  const float* __restrict__ mean,
                                  const float* __restrict__ logv,
                                  float* __restrict__ slots)
{
    int idx = blockIdx.x * 256 + threadIdx.x;
    int d = idx & 255;
    slots[idx] = mean[d] + expf(logv[d]) * noise[idx];
}

// LN(inputs) -> bf16 [M,256]
__global__ void ln_kv_kernel(const float* __restrict__ src, __nv_bfloat16* __restrict__ dst,
                             const float* __restrict__ w, const float* __restrict__ b)
{
    int row = blockIdx.x * 8 + (threadIdx.x >> 5);
    int lane = threadIdx.x & 31;
    const float4* r4 = (const float4*)(src + (size_t)row * 256);
    float4 v0 = r4[lane], v1 = r4[lane + 32];
    float s  = v0.x + v0.y + v0.z + v0.w + v1.x + v1.y + v1.z + v1.w;
    float sq = v0.x*v0.x + v0.y*v0.y + v0.z*v0.z + v0.w*v0.w
             + v1.x*v1.x + v1.y*v1.y + v1.z*v1.z + v1.w*v1.w;
#pragma unroll
    for (int o = 16; o > 0; o >>= 1) {
        s  += __shfl_xor_sync(~0u, s,  o);
        sq += __shfl_xor_sync(~0u, sq, o);
    }
    float mean = s * (1.0f/256.0f);
    float rstd = rsqrtf(sq * (1.0f/256.0f) - mean*mean + LN_EPSc);
    float4 wa = ((const float4*)w)[lane], wb = ((const float4*)w)[lane+32];
    float4 ba = ((const float4*)b)[lane], bb = ((const float4*)b)[lane+32];
    float4 o0, o1;
    o0.x=(v0.x-mean)*rstd*wa.x+ba.x; o0.y=(v0.y-mean)*rstd*wa.y+ba.y;
    o0.z=(v0.z-mean)*rstd*wa.z+ba.z; o0.w=(v0.w-mean)*rstd*wa.w+ba.w;
    o1.x=(v1.x-mean)*rstd*wb.x+bb.x; o1.y=(v1.y-mean)*rstd*wb.y+bb.y;
    o1.z=(v1.z-mean)*rstd*wb.z+bb.z; o1.w=(v1.w-mean)*rstd*wb.w+bb.w;
    __nv_bfloat16* dr = dst + (size_t)row * 256;
    __nv_bfloat162 h0; h0.x = __float2bfloat16(o0.x); h0.y = __float2bfloat16(o0.y);
    __nv_bfloat162 h1; h1.x = __float2bfloat16(o0.z); h1.y = __float2bfloat16(o0.w);
    __nv_bfloat162 h2; h2.x = __float2bfloat16(o1.x); h2.y = __float2bfloat16(o1.y);
    __nv_bfloat162 h3; h3.x = __float2bfloat16(o1.z); h3.y = __float2bfloat16(o1.w);
    ((__nv_bfloat162*)(dr + lane*4))[0] = h0;
    ((__nv_bfloat162*)(dr + lane*4))[1] = h1;
    ((__nv_bfloat162*)(dr + 128 + lane*4))[0] = h2;
    ((__nv_bfloat162*)(dr + 128 + lane*4))[1] = h3;
}

// W -> [n][k] K-major bf16 (n<256: wk, else wv)
__global__ void prep_w_kernel(const float* __restrict__ wk, const float* __restrict__ wv,
                              __nv_bfloat16* __restrict__ B2)
{
    int n = blockIdx.x;
    int k = threadIdx.x;
    const float* W = (n < 256) ? wk : wv;
    B2[(size_t)n * 256 + k] = __float2bfloat16(W[(size_t)k * 256 + (n & 255)]);
}

// ---------------- K/V GEMM: pure bf16, 4 chunks of K=64 ----------------------
#define KV_SMEM (32768 * 2)
__global__ __launch_bounds__(256, 2)
void kv_gemm_mma(const __nv_bfloat16* __restrict__ A2, const __nv_bfloat16* __restrict__ B2,
                 const float* __restrict__ bk, const float* __restrict__ bv,
                 __nv_bfloat16* __restrict__ Kout, __nv_bfloat16* __restrict__ Vout)
{
    extern __shared__ char dsm[];
    uint32_t sbase = smem_u32(dsm);
    int tid = threadIdx.x, lane = tid & 31, wid = tid >> 5;
    int warp_m = wid & 1, warp_n = wid >> 1;
    int cb  = blockIdx.x;
    int m0  = blockIdx.y * 128;
    int mat = cb >> 1, nh = cb & 1;
    const float* bias = mat ? bv : bk;
    __nv_bfloat16* Out = mat ? Vout : Kout;

    float acc[4][4][4];
#pragma unroll
    for (int a = 0; a < 4; ++a)
#pragma unroll
        for (int b = 0; b < 4; ++b)
#pragma unroll
            for (int r = 0; r < 4; ++r) acc[a][b][r] = 0.0f;

    int lr = tid >> 3, lj = tid & 7;
    int brow_g = mat * 256 + nh * 128;

    int l7 = lane & 7, l15 = lane & 15, lhA = lane >> 4;
    int nrow_loc = (lane >> 4) * 8 + l7, hB = (lane >> 3) & 1;
    uint32_t aRow[4], bRow[2];
#pragma unroll
    for (int mt = 0; mt < 4; ++mt) aRow[mt] = (uint32_t)(warp_m*64 + mt*16 + l15) << 7;
#pragma unroll
    for (int g = 0; g < 2; ++g) bRow[g] = (uint32_t)(warp_n*32 + g*16 + nrow_loc) << 7;

#define LOAD_CHUNK(c, stg) do {                                               \
    uint32_t sa = sbase + (stg)*32768;                                        \
    int ko = (c)*64;                                                          \
    _Pragma("unroll")                                                         \
    for (int i = 0; i < 4; ++i) {                                             \
        int r = lr + i*32;                                                    \
        uint32_t so = (r<<7) + ((lj ^ (r&7))<<4);                             \
        cp_async16(sa + so, A2 + (size_t)(m0 + r)*256 + ko + lj*8);           \
        cp_async16(sa + 16384 + so, B2 + (size_t)(brow_g + r)*256 + ko + lj*8);\
    }                                                                         \
    CP_COMMIT();                                                              \
} while (0)

    LOAD_CHUNK(0, 0);
    LOAD_CHUNK(1, 1);

    for (int c = 0; c < 4; ++c) {
        if (c == 3) { CP_WAIT0(); } else { CP_WAIT1(); }
        __syncthreads();
        uint32_t sa = sbase + (c & 1) * 32768;
#pragma unroll
        for (int ks = 0; ks < 4; ++ks) {
            uint32_t achk = (uint32_t)(((2*ks + lhA) ^ l7) << 4);
            uint32_t bchk = (uint32_t)(((2*ks + hB)  ^ l7) << 4);
            uint32_t af[4][4], bf[2][4];
#pragma unroll
            for (int mt = 0; mt < 4; ++mt)
                LDMX4(af[mt][0], af[mt][1], af[mt][2], af[mt][3], sa + aRow[mt] + achk);
#pragma unroll
            for (int g = 0; g < 2; ++g)
                LDMX4(bf[g][0], bf[g][1], bf[g][2], bf[g][3], sa + 16384 + bRow[g] + bchk);
#pragma unroll
            for (int mt = 0; mt < 4; ++mt)
#pragma unroll
                for (int nt = 0; nt < 4; ++nt)
                    MMA16816(acc[mt][nt], af[mt][0], af[mt][1], af[mt][2], af[mt][3],
                             bf[nt>>1][(nt&1)*2], bf[nt>>1][(nt&1)*2+1]);
        }
        __syncthreads();
        if (c + 2 < 4) LOAD_CHUNK(c + 2, c & 1);
    }

    int col_base = nh * 128 + warp_n * 32;
    int h = col_base >> 5;
#pragma unroll
    for (int mt = 0; mt < 4; ++mt) {
#pragma unroll
        for (int half = 0; half < 2; ++half) {
            int m = m0 + warp_m * 64 + mt * 16 + (lane >> 2) + half * 8;
            int bi = m >> 12, nn = m & 4095;
            __nv_bfloat16* dst = Out + ((size_t)(bi * 8 + h) * 4096 + nn) * 32;
#pragma unroll
            for (int nt = 0; nt < 4; ++nt) {
                int dh = nt * 8 + (lane & 3) * 2;
                __nv_bfloat162 o;
                o.x = __float2bfloat16(acc[mt][nt][half*2+0] + bias[col_base + dh]);
                o.y = __float2bfloat16(acc[mt][nt][half*2+1] + bias[col_base + dh + 1]);
                *(__nv_bfloat162*)(dst + dh) = o;
            }
        }
    }
#undef LOAD_CHUNK
}

// ---------------- small GEMM (512 rows), optional fused input-LN -------------
// modes: 0 plain, 1 relu, 2 residual add, 3 q-layout remap,
//        4 virtual-A: A = (sum_c upd_part[c]) * inv_rs (resid = rs_part)
__global__ __launch_bounds__(256)
void gemm512_kernel(const float* __restrict__ Ain, const float* __restrict__ Win,
                    const float* __restrict__ biasin, float* __restrict__ outin,
                    int Ncols, int mode, const float* __restrict__ resid,
                    const float* __restrict__ lnw, const float* __restrict__ lnb,
                    const float* __restrict__ A2, const float* __restrict__ W2,
                    const float* __restrict__ bias2, float* __restrict__ out2,
                    int y2)
{
    __shared__ float As[64][36];
    __shared__ float Bs[64][68];
    __shared__ float s_mean[32], s_rstd[32];
    __shared__ float s_inv[256];
    int tid = threadIdx.x, tx = tid & 31, ty = tid >> 5;
    int c0 = tx*2, r0 = ty*4;
    int m0 = blockIdx.x * 32;
    int yb = blockIdx.y;
    const float* A = Ain; const float* W = Win; const float* bias = biasin;
    float* out = outin;
    if (yb >= y2) { A = A2; W = W2; bias = bias2; out = out2; yb -= y2; }
    int n0 = yb * 64;
    int do_ln = (lnw != nullptr);

    if (do_ln) {
        int r = ty * 4 + (tx >> 3);
        const float4* rp = (const float4*)(A + (size_t)(m0 + r) * 256);
        float s = 0.0f, sq = 0.0f;
        for (int j = (tx & 7); j < 64; j += 8) {
            float4 v = rp[j];
            s  += v.x + v.y + v.z + v.w;
            sq += v.x*v.x + v.y*v.y + v.z*v.z + v.w*v.w;
        }
#pragma unroll
        for (int o = 4; o > 0; o >>= 1) {
            s  += __shfl_xor_sync(~0u, s,  o);
            sq += __shfl_xor_sync(~0u, sq, o);
        }
        if ((tx & 7) == 0) {
            float mean = s * (1.0f/256.0f);
            s_mean[r] = mean;
            s_rstd[r] = rsqrtf(sq * (1.0f/256.0f) - mean*mean + LN_EPSc);
        }
    }
    if (mode == 4) {
        int r = tid >> 3, hh = tid & 7;
        int m = m0 + r, b = m >> 3, s = m & 7;
        int bh = b * 8 + hh;
        float t = resid[(size_t)(bh*4+0)*8 + s] + resid[(size_t)(bh*4+1)*8 + s]
                + resid[(size_t)(bh*4+2)*8 + s] + resid[(size_t)(bh*4+3)*8 + s];
        s_inv[r*8 + hh] = 1.0f / fmaxf(t, 1e-12f);
    }
    __syncthreads();

    float acc[4][2] = {};
    for (int kt = 0; kt < 4; ++kt) {
        __syncthreads();
#pragma unroll
        for (int i = 0; i < 2; ++i) {
            int fid = tid*2 + i, ar = fid >> 4, kq = fid & 15;
            float4 va;
            if (mode == 4) {
                int m = m0 + ar, b = m >> 3, s = m & 7;
                int c = kt*64 + kq*4;
                int h = c >> 5, cc = c & 31;
                size_t base = ((size_t)(b*8 + h) * 4) * 256 + s*32 + cc;
                float4 v0 = *(const float4*)(A + base);
                float4 v1 = *(const float4*)(A + base + 256);
                float4 v2 = *(const float4*)(A + base + 512);
                float4 v3 = *(const float4*)(A + base + 768);
                float iv = s_inv[ar*8 + h];
                va.x = (v0.x+v1.x+v2.x+v3.x)*iv;
                va.y = (v0.y+v1.y+v2.y+v3.y)*iv;
                va.z = (v0.z+v1.z+v2.z+v3.z)*iv;
                va.w = (v0.w+v1.w+v2.w+v3.w)*iv;
            } else {
                va = *(const float4*)(A + (size_t)(m0+ar)*256 + kt*64 + kq*4);
                if (do_ln) {
                    float mn = s_mean[ar], rs = s_rstd[ar];
                    float4 lw = *(const float4*)(lnw + kt*64 + kq*4);
                    float4 lb = *(const float4*)(lnb + kt*64 + kq*4);
                    va.x = (va.x - mn)*rs*lw.x + lb.x;
                    va.y = (va.y - mn)*rs*lw.y + lb.y;
                    va.z = (va.z - mn)*rs*lw.z + lb.z;
                    va.w = (va.w - mn)*rs*lw.w + lb.w;
                }
            }
            As[kq*4+0][ar]=va.x; As[kq*4+1][ar]=va.y; As[kq*4+2][ar]=va.z; As[kq*4+3][ar]=va.w;
        }
#pragma unroll
        for (int j = 0; j < 4; ++j) {
            int fid = tid + j*256, br = fid >> 4, c4 = fid & 15;
            *(float4*)&Bs[br][c4*4] = *(const float4*)(W + (size_t)(kt*64+br)*Ncols + n0 + c4*4);
        }
        __syncthreads();
#pragma unroll 8
        for (int k = 0; k < 64; ++k) {
            float4 a4 = *(const float4*)&As[k][r0];
            float2 b2 = *(const float2*)&Bs[k][c0];
            acc[0][0]+=a4.x*b2.x; acc[0][1]+=a4.x*b2.y;
            acc[1][0]+=a4.y*b2.x; acc[1][1]+=a4.y*b2.y;
            acc[2][0]+=a4.z*b2.x; acc[2][1]+=a4.z*b2.y;
            acc[3][0]+=a4.w*b2.x; acc[3][1]+=a4.w*b2.y;
        }
    }
#pragma unroll
    for (int i = 0; i < 4; ++i)
#pragma unroll
        for (int j = 0; j < 2; ++j) {
            int m = m0 + r0 + i, n = n0 + c0 + j;
            float v = acc[i][j] + bias[n];
            if (mode == 1)      out[(size_t)m*Ncols + n] = fmaxf(v, 0.0f);
            else if (mode == 2) out[(size_t)m*256 + n] = resid[(size_t)m*256 + n] + v;
            else if (mode == 3) {
                int bq = m >> 3, s = m & 7, h = n >> 5, dh = n & 31;
                out[((size_t)(bq*8 + h)*8 + s)*32 + dh] = v;
            }
            else                out[(size_t)m*Ncols + n] = v;  // modes 0, 4
        }
}

// ---------------- attention, n-chunked (4 chunks of 1024), K+V bf16 ----------
#define ATT_SMEM ((8192 + 256 + 64 + 2048) * sizeof(float))
__global__ __launch_bounds__(256)
void attention_part(const float* __restrict__ q, const __nv_bfloat16* __restrict__ Kh,
                    const __nv_bfloat16* __restrict__ Vh,
                    float* __restrict__ upd_part, float* __restrict__ rs_part,
                    float* __restrict__ attn_out, int write_attn)
{
    extern __shared__ float sm[];
    float* attn_s = sm;                   // [8][1024]
    float* q_s    = sm + 8192;            // [8][32]
    float* red    = sm + 8192 + 256;      // [8][8]
    float* red2   = sm + 8192 + 256 + 64; // [8 warps][8 s][32 dh]
    int bh = blockIdx.x, chunk = blockIdx.y;
    int tid = threadIdx.x, lane = tid & 31, wid = tid >> 5;
    int n0 = chunk * 1024;

    q_s[tid] = q[(size_t)bh*256 + tid] * 0.0625f;  // scale = D^-0.5 = 1/16
    __syncthreads();

    float rs[8] = {};
    const __nv_bfloat16* Kb = Kh + (size_t)bh * 4096 * 32;
    for (int it = 0; it < 4; ++it) {
        int nl = it*256 + tid;
        const __nv_bfloat16* kr = Kb + (size_t)(n0 + nl) * 32;
        float d[8] = {};
#pragma unroll
        for (int c4 = 0; c4 < 4; ++c4) {
            float4 raw = *(const float4*)(kr + c4*8);
            const __nv_bfloat162* kp = (const __nv_bfloat162*)&raw;
            float2 k0 = __bfloat1622float2(kp[0]);
            float2 k1 = __bfloat1622float2(kp[1]);
            float2 k2 = __bfloat1622float2(kp[2]);
            float2 k3 = __bfloat1622float2(kp[3]);
#pragma unroll
            for (int s = 0; s < 8; ++s) {
                float4 qa = *(const float4*)(q_s + s*32 + c4*8);
                float4 qb = *(const float4*)(q_s + s*32 + c4*8 + 4);
                d[s] += k0.x*qa.x + k0.y*qa.y + k1.x*qa.z + k1.y*qa.w
                      + k2.x*qb.x + k2.y*qb.y + k3.x*qb.z + k3.y*qb.w;
            }
        }
        float mx = d[0];
#pragma unroll
        for (int s = 1; s < 8; ++s) mx = fmaxf(mx, d[s]);
        float e[8], sum = 0.0f;
#pragma unroll
        for (int s = 0; s < 8; ++s) { e[s] = __expf(d[s]-mx); sum += e[s]; }
        float inv = __fdividef(1.0f, sum);
#pragma unroll
        for (int s = 0; s < 8; ++s) {
            float p = e[s]*inv + EPSc;
            attn_s[s*1024 + nl] = p;
            rs[s] += p;
        }
    }
#pragma unroll
    for (int s = 0; s < 8; ++s)
#pragma unroll
        for (int o = 16; o > 0; o >>= 1) rs[s] += __shfl_xor_sync(~0u, rs[s], o);
    if (lane == 0)
#pragma unroll
        for (int s = 0; s < 8; ++s) red[wid*8 + s] = rs[s];
    __syncthreads();
    if (tid < 8) {
        float t = 0.0f;
#pragma unroll
        for (int w = 0; w < 8; ++w) t += red[w*8 + tid];
        rs_part[(size_t)(bh*4 + chunk)*8 + tid] = t;
    }

    // pass2: warp w owns n-substripe [w*128, (w+1)*128) of this chunk
    {
        const __nv_bfloat16* Vb = Vh + (size_t)bh * 4096 * 32;
        float acc[8] = {};
        int nb = wid * 128;
        for (int nl = nb; nl < nb + 128; nl += 4) {
            float4 a[8];
#pragma unroll
            for (int s = 0; s < 8; ++s) a[s] = *(const float4*)(attn_s + s*1024 + nl);
            int n = n0 + nl;
            float v0 = __bfloat162float(Vb[(size_t)(n+0)*32 + lane]);
            float v1 = __bfloat162float(Vb[(size_t)(n+1)*32 + lane]);
            float v2 = __bfloat162float(Vb[(size_t)(n+2)*32 + lane]);
            float v3 = __bfloat162float(Vb[(size_t)(n+3)*32 + lane]);
#pragma unroll
            for (int s = 0; s < 8; ++s)
                acc[s] += a[s].x*v0 + a[s].y*v1 + a[s].z*v2 + a[s].w*v3;
        }
#pragma unroll
        for (int s = 0; s < 8; ++s) red2[(wid*8 + s)*32 + lane] = acc[s];
    }
    __syncthreads();
    {
        int s = tid >> 5, dh = tid & 31;
        float t = 0.0f;
#pragma unroll
        for (int w = 0; w < 8; ++w) t += red2[(w*8 + s)*32 + dh];
        upd_part[(size_t)(bh*4 + chunk)*256 + s*32 + dh] = t;
    }

    if (write_attn) {  // unnormalized p; scaled later by attn_scale
        float* ao = attn_out + (size_t)bh * 32768 + n0;
        for (int i = tid; i < 8192; i += 256)
            ao[(i >> 10) * 4096 + (i & 1023)] = attn_s[i];
    }
}

__global__ void attn_scale(float* __restrict__ ao, const float* __restrict__ rsp)
{
    int bh = blockIdx.x, tid = threadIdx.x;
    __shared__ float inv[8];
    if (tid < 8) {
        float t = 0.0f;
#pragma unroll
        for (int c = 0; c < 4; ++c) t += rsp[(size_t)(bh*4 + c)*8 + tid];
        inv[tid] = 1.0f / fmaxf(t, 1e-12f);
    }
    __syncthreads();
    float* p = ao + (size_t)bh * 32768;
    for (int i = tid; i < 32768; i += 256)
        p[i] *= inv[i >> 12];
}

__global__ void gru_combine_kernel(const float* __restrict__ xg,
                                   const float* __restrict__ hg,
                                   float* __restrict__ slots)
{
    int idx = blockIdx.x * 256 + threadIdx.x;
    int row = idx >> 8, c = idx & 255;
    const float* x = xg + (size_t)row * 768;
    const float* h = hg + (size_t)row * 768;
    float r = 1.0f / (1.0f + expf(-(x[c]     + h[c])));
    float z = 1.0f / (1.0f + expf(-(x[256+c] + h[256+c])));
    float n = tanhf(x[512+c] + r * h[512+c]);
    slots[idx] = (1.0f - z) * n + z * slots[idx];
}

// ---------------- launcher ----------------------------------------------------
extern "C" void kernel_launch(void* const* d_in, const int* in_sizes, int n_in,
                              void* d_out, int out_size)
{
    const float* inp   = (const float*)d_in[0];
    const float* noise = (const float*)d_in[1];
    const float* smean = (const float*)d_in[2];
    const float* slogv = (const float*)d_in[3];
    const float* wq = (const float*)d_in[4];  const float* bq = (const float*)d_in[5];
    const float* wk = (const float*)d_in[6];  const float* bk = (const float*)d_in[7];
    const float* wv = (const float*)d_in[8];  const float* bv = (const float*)d_in[9];
    const float* wo = (const float*)d_in[10]; const float* bo = (const float*)d_in[11];
    const float* w_ih = (const float*)d_in[12]; const float* b_ih = (const float*)d_in[13];
    const float* w_hh = (const float*)d_in[14]; const float* b_hh = (const float*)d_in[15];
    const float* w1 = (const float*)d_in[16]; const float* b1 = (const float*)d_in[17];
    const float* w2 = (const float*)d_in[18]; const float* b2 = (const float*)d_in[19];
    const float* lin_w = (const float*)d_in[20]; const float* lin_b = (const float*)d_in[21];
    const float* ls_w  = (const float*)d_in[22]; const float* ls_b  = (const float*)d_in[23];
    const float* lff_w = (const float*)d_in[24]; const float* lff_b = (const float*)d_in[25];

    float* out      = (float*)d_out;
    float* attn_out = out + 131072;

    __nv_bfloat16 *a2, *wb2, *kbh, *vbh;
    float *slots,*qb,*upd2,*h1,*xg,*hg,*updp,*rsp;
    cudaGetSymbolAddress((void**)&a2,   g_a2);
    cudaGetSymbolAddress((void**)&wb2,  g_wb2);
    cudaGetSymbolAddress((void**)&kbh,  g_kbufh);
    cudaGetSymbolAddress((void**)&vbh,  g_vbufh);
    cudaGetSymbolAddress((void**)&slots,g_slots);
    cudaGetSymbolAddress((void**)&qb,   g_q);
    cudaGetSymbolAddress((void**)&upd2, g_upd2);
    cudaGetSymbolAddress((void**)&h1,   g_h1);
    cudaGetSymbolAddress((void**)&xg,   g_xg);
    cudaGetSymbolAddress((void**)&hg,   g_hg);
    cudaGetSymbolAddress((void**)&updp, g_updpart);
    cudaGetSymbolAddress((void**)&rsp,  g_rspart);

    cudaFuncSetAttribute(attention_part,
                         cudaFuncAttributeMaxDynamicSharedMemorySize, (int)ATT_SMEM);
    cudaFuncSetAttribute(kv_gemm_mma,
                         cudaFuncAttributeMaxDynamicSharedMemorySize, KV_SMEM);

    init_slots_kernel<<<BSc, 256>>>(noise, smean, slogv, slots);
    prep_w_kernel<<<512, 256>>>(wk, wv, wb2);
    ln_kv_kernel<<<Mc/8, 256>>>(inp, a2, lin_w, lin_b);
    kv_gemm_mma<<<dim3(4, Mc/128), 256, KV_SMEM>>>(a2, wb2, bk, bv, kbh, vbh);

    for (int it = 0; it < ITERS; ++it) {
        int last = (it == ITERS - 1);
        // q = LN(slots) @ wq (LN fused), remap to [B,H,S,DH]
        gemm512_kernel<<<dim3(16, 4), 256>>>(slots, wq, bq, qb, 256, 3, nullptr,
                                             ls_w, ls_b, nullptr, nullptr, nullptr, nullptr, 9999);
        attention_part<<<dim3(512, 4), 256, ATT_SMEM>>>(qb, kbh, vbh, updp, rsp, attn_out, last);
        // upd2 = (normalized upd from parts) @ wo + bo   (finalize fused, mode 4)
        gemm512_kernel<<<dim3(16, 4), 256>>>(updp, wo, bo, upd2, 256, 4, rsp,
                                             nullptr, nullptr, nullptr, nullptr, nullptr, nullptr, 9999);
        gemm512_kernel<<<dim3(16, 24), 256>>>(upd2, w_ih, b_ih, xg, 768, 0, nullptr,
                                              nullptr, nullptr, slots, w_hh, b_hh, hg, 12);
        gru_combine_kernel<<<BSc, 256>>>(xg, hg, slots);
        gemm512_kernel<<<dim3(16, 4), 256>>>(slots, w1, b1, h1, 256, 1, nullptr,
                                             lff_w, lff_b, nullptr, nullptr, nullptr, nullptr, 9999);
        gemm512_kernel<<<dim3(16, 4), 256>>>(h1, w2, b2, last ? out : slots, 256, 2, slots,
                                             nullptr, nullptr, nullptr, nullptr, nullptr, nullptr, 9999);
        if (last) attn_scale<<<512, 256>>>(attn_out, rsp);
    }
}